// round 8
// baseline (speedup 1.0000x reference)
#include <cuda_runtime.h>

#define NN   200000
#define DIM  64
#define NV   (NN * DIM)
#define EMAX 1250000
#define ALPHA 0.25f
#define NB_SCAN ((NN + 1023) / 1024)   // 196

// Scratch (device globals — no allocation allowed).
// NOTE: never pass these symbols from host code; select inside kernels.
// g_x1/g_x2 hold the ACTIVE dim-block only: [NN][32] compact (row stride 32).
__device__ float g_x1[NN * 32];
__device__ float g_x2[NN * 32];
__device__ float g_out[NV];
__device__ float g_dis[NN];
__device__ int   g_deg[NN];
__device__ int   g_off[NN];
__device__ int   g_cur[NN];
__device__ int   g_bsum[NB_SCAN];
__device__ int   g_bpre[NB_SCAN];
__device__ int   g_src[EMAX];
__device__ float g_wgt[EMAX];

// ---- degree / normalization (R4-proven pipeline) ----
__global__ void k_deg0() {
    int i = blockIdx.x * blockDim.x + threadIdx.x;
    if (i < NN) { g_deg[i] = 0; g_cur[i] = 0; }
}

__global__ void k_count(const int* __restrict__ col, int E) {
    int i = blockIdx.x * blockDim.x + threadIdx.x;
    if (i < E) atomicAdd(&g_deg[col[i]], 1);
}

__global__ void k_dis() {
    int i = blockIdx.x * blockDim.x + threadIdx.x;
    if (i < NN) {
        int d = g_deg[i];
        g_dis[i] = (d > 0) ? rsqrtf((float)d) : 0.f;
    }
}

__global__ void k_scan1() {
    __shared__ int s[1024];
    int tid = threadIdx.x;
    int i = blockIdx.x * 1024 + tid;
    int v = (i < NN) ? g_deg[i] : 0;
    s[tid] = v;
    __syncthreads();
    #pragma unroll
    for (int o = 1; o < 1024; o <<= 1) {
        int t = (tid >= o) ? s[tid - o] : 0;
        __syncthreads();
        s[tid] += t;
        __syncthreads();
    }
    if (i < NN) g_off[i] = s[tid] - v;
    if (tid == 1023) g_bsum[blockIdx.x] = s[1023];
}

__global__ void k_scan2() {
    __shared__ int s[256];
    int tid = threadIdx.x;
    int v = (tid < NB_SCAN) ? g_bsum[tid] : 0;
    s[tid] = v;
    __syncthreads();
    #pragma unroll
    for (int o = 1; o < 256; o <<= 1) {
        int t = (tid >= o) ? s[tid - o] : 0;
        __syncthreads();
        s[tid] += t;
        __syncthreads();
    }
    if (tid < NB_SCAN) g_bpre[tid] = s[tid] - v;
}

__global__ void k_off_final() {
    int i = blockIdx.x * blockDim.x + threadIdx.x;
    if (i < NN) g_off[i] += g_bpre[i >> 10];
}

__global__ void k_fill(const int* __restrict__ row, const int* __restrict__ col, int E) {
    int e = blockIdx.x * blockDim.x + threadIdx.x;
    if (e >= E) return;
    int r = __ldg(row + e);
    int c = __ldg(col + e);
    int slot = __ldg(g_off + c) + atomicAdd(&g_cur[c], 1);
    g_src[slot] = r;
    g_wgt[slot] = __ldg((const float*)g_dis + r) * __ldg((const float*)g_dis + c);
}

// ======== dim-blocked gather SpMM: 32 dims per phase, L2-resident ========
// 16 lanes per node, float2 per lane (one 128B line per gathered row).
// Unroll-4 with 4 independent accumulators.

// layer 0: emb[:, b*32 : b*32+32] -> g_x1 (compact [NN][32])
// layer 1: g_x1 -> g_x2
__global__ void k_gather(const float* __restrict__ emb, int layer, int blk) {
    int t = blockIdx.x * blockDim.x + threadIdx.x;
    int node = t >> 4;
    int j = t & 15;
    if (node >= NN) return;

    // source row base in float2 units + row stride in float2 units
    const float2* x;
    size_t stride, coff;
    if (layer == 0) { x = (const float2*)emb; stride = 32; coff = (size_t)blk * 16 + j; }
    else            { x = (const float2*)g_x1; stride = 16; coff = j; }
    float2* xn = (layer == 0) ? (float2*)g_x1 : (float2*)g_x2;

    int beg = __ldg(g_off + node);
    int deg = __ldg(g_deg + node);

    float2 A0 = make_float2(0.f, 0.f), A1 = A0, A2 = A0, A3 = A0;

    int k = 0;
    for (; k + 4 <= deg; k += 4) {
        int r0 = __ldg(g_src + beg + k);
        int r1 = __ldg(g_src + beg + k + 1);
        int r2 = __ldg(g_src + beg + k + 2);
        int r3 = __ldg(g_src + beg + k + 3);
        float w0 = __ldg(g_wgt + beg + k);
        float w1 = __ldg(g_wgt + beg + k + 1);
        float w2 = __ldg(g_wgt + beg + k + 2);
        float w3 = __ldg(g_wgt + beg + k + 3);
        float2 v0 = __ldg(x + (size_t)r0 * stride + coff);
        float2 v1 = __ldg(x + (size_t)r1 * stride + coff);
        float2 v2 = __ldg(x + (size_t)r2 * stride + coff);
        float2 v3 = __ldg(x + (size_t)r3 * stride + coff);
        A0.x += w0 * v0.x; A0.y += w0 * v0.y;
        A1.x += w1 * v1.x; A1.y += w1 * v1.y;
        A2.x += w2 * v2.x; A2.y += w2 * v2.y;
        A3.x += w3 * v3.x; A3.y += w3 * v3.y;
    }
    if (k + 2 <= deg) {
        int r0 = __ldg(g_src + beg + k);
        int r1 = __ldg(g_src + beg + k + 1);
        float w0 = __ldg(g_wgt + beg + k);
        float w1 = __ldg(g_wgt + beg + k + 1);
        float2 v0 = __ldg(x + (size_t)r0 * stride + coff);
        float2 v1 = __ldg(x + (size_t)r1 * stride + coff);
        A0.x += w0 * v0.x; A0.y += w0 * v0.y;
        A1.x += w1 * v1.x; A1.y += w1 * v1.y;
        k += 2;
    }
    if (k < deg) {
        int r0 = __ldg(g_src + beg + k);
        float w0 = __ldg(g_wgt + beg + k);
        float2 v0 = __ldg(x + (size_t)r0 * stride + coff);
        A2.x += w0 * v0.x; A2.y += w0 * v0.y;
    }

    float2 acc;
    acc.x = (A0.x + A1.x) + (A2.x + A3.x);
    acc.y = (A0.y + A1.y) + (A2.y + A3.y);
    xn[(size_t)node * 16 + j] = acc;
}

// final layer for block blk, fused with alpha-combine:
// out[:, blk] = 0.25*(emb[:, blk] + x1 + x2 + gather(x2))
__global__ void k_gather_final(const float* __restrict__ emb, int blk) {
    int t = blockIdx.x * blockDim.x + threadIdx.x;
    int node = t >> 4;
    int j = t & 15;
    if (node >= NN) return;

    const float2* x = (const float2*)g_x2;
    int beg = __ldg(g_off + node);
    int deg = __ldg(g_deg + node);

    float2 A0 = make_float2(0.f, 0.f), A1 = A0, A2 = A0, A3 = A0;

    int k = 0;
    for (; k + 4 <= deg; k += 4) {
        int r0 = __ldg(g_src + beg + k);
        int r1 = __ldg(g_src + beg + k + 1);
        int r2 = __ldg(g_src + beg + k + 2);
        int r3 = __ldg(g_src + beg + k + 3);
        float w0 = __ldg(g_wgt + beg + k);
        float w1 = __ldg(g_wgt + beg + k + 1);
        float w2 = __ldg(g_wgt + beg + k + 2);
        float w3 = __ldg(g_wgt + beg + k + 3);
        float2 v0 = __ldg(x + (size_t)r0 * 16 + j);
        float2 v1 = __ldg(x + (size_t)r1 * 16 + j);
        float2 v2 = __ldg(x + (size_t)r2 * 16 + j);
        float2 v3 = __ldg(x + (size_t)r3 * 16 + j);
        A0.x += w0 * v0.x; A0.y += w0 * v0.y;
        A1.x += w1 * v1.x; A1.y += w1 * v1.y;
        A2.x += w2 * v2.x; A2.y += w2 * v2.y;
        A3.x += w3 * v3.x; A3.y += w3 * v3.y;
    }
    if (k + 2 <= deg) {
        int r0 = __ldg(g_src + beg + k);
        int r1 = __ldg(g_src + beg + k + 1);
        float w0 = __ldg(g_wgt + beg + k);
        float w1 = __ldg(g_wgt + beg + k + 1);
        float2 v0 = __ldg(x + (size_t)r0 * 16 + j);
        float2 v1 = __ldg(x + (size_t)r1 * 16 + j);
        A0.x += w0 * v0.x; A0.y += w0 * v0.y;
        A1.x += w1 * v1.x; A1.y += w1 * v1.y;
        k += 2;
    }
    if (k < deg) {
        int r0 = __ldg(g_src + beg + k);
        float w0 = __ldg(g_wgt + beg + k);
        float2 v0 = __ldg(x + (size_t)r0 * 16 + j);
        A2.x += w0 * v0.x; A2.y += w0 * v0.y;
    }

    size_t cidx = (size_t)node * 16 + j;                  // compact index
    size_t fidx = (size_t)node * 32 + (size_t)blk * 16 + j; // full-row f2 index
    float2 a = __ldg((const float2*)emb + fidx);
    float2 b = ((const float2*)g_x1)[cidx];
    float2 c = ((const float2*)g_x2)[cidx];
    float2 o;
    o.x = ALPHA * (a.x + b.x + c.x + ((A0.x + A1.x) + (A2.x + A3.x)));
    o.y = ALPHA * (a.y + b.y + c.y + ((A0.y + A1.y) + (A2.y + A3.y)));
    ((float2*)g_out)[fidx] = o;
}

// ---- scoring: 16 lanes per (user,item) pair, float4 loads ----
__global__ void k_score(const int* __restrict__ batch, float* __restrict__ out, int P) {
    int t = blockIdx.x * blockDim.x + threadIdx.x;
    int p = t >> 4;
    int lane = t & 15;
    if (p >= P) return;
    int u = __ldg(batch + 3 * p);
    int v = __ldg(batch + 3 * p + 1);
    float4 a = __ldg((const float4*)g_out + (size_t)u * 16 + lane);
    float4 b = __ldg((const float4*)g_out + (size_t)v * 16 + lane);
    float s = a.x * b.x + a.y * b.y + a.z * b.z + a.w * b.w;
    #pragma unroll
    for (int o = 8; o; o >>= 1) s += __shfl_xor_sync(0xFFFFFFFFu, s, o);
    if (lane == 0) out[p] = s;
}

extern "C" void kernel_launch(void* const* d_in, const int* in_sizes, int n_in,
                              void* d_out, int out_size) {
    const float* emb   = (const float*)d_in[0];
    const int*   ei    = (const int*)d_in[1];
    const int*   batch = (const int*)d_in[2];
    float*       out   = (float*)d_out;

    int E = in_sizes[1] / 2;
    const int* row = ei;
    const int* col = ei + E;
    int P = in_sizes[2] / 3;

    k_deg0<<<(NN + 255) / 256, 256>>>();
    k_count<<<(E + 255) / 256, 256>>>(col, E);
    k_dis<<<(NN + 255) / 256, 256>>>();
    k_scan1<<<NB_SCAN, 1024>>>();
    k_scan2<<<1, 256>>>();
    k_off_final<<<(NN + 255) / 256, 256>>>();
    k_fill<<<(E + 255) / 256, 256>>>(row, col, E);

    int gthreads = NN * 16;
    int gblocks = (gthreads + 255) / 256;
    // dim-block 0: all 3 layers, then dim-block 1
    for (int blk = 0; blk < 2; blk++) {
        k_gather<<<gblocks, 256>>>(emb, 0, blk);
        k_gather<<<gblocks, 256>>>(emb, 1, blk);
        k_gather_final<<<gblocks, 256>>>(emb, blk);
    }

    long long sthreads = (long long)P * 16;
    k_score<<<(int)((sthreads + 255) / 256), 256>>>(batch, out, P);
}

// round 9
// speedup vs baseline: 1.0083x; 1.0083x over previous
#include <cuda_runtime.h>

#define NN   200000
#define DIM  64
#define NV   (NN * DIM)
#define EMAX 1250000
#define EPAD (EMAX + NN)          // each node pads at most 1 slot (to even)
#define ALPHA 0.25f
#define NB_SCAN ((NN + 1023) / 1024)   // 196

// Scratch (device globals — no allocation allowed).
// NOTE: never pass these symbols from host code; select inside kernels.
__device__ float g_x1[NV];
__device__ float g_x2[NV];
__device__ float g_out[NV];
__device__ float g_dis[NN];
__device__ int   g_deg[NN];
__device__ int   g_off[NN];      // offsets over PADDED degrees (even per node)
__device__ int   g_cur[NN];
__device__ int   g_bsum[NB_SCAN];
__device__ int   g_bpre[NB_SCAN];
__device__ int2  g_pack[EPAD];   // (src, wgt-bits); padded slots = (0, 0.0f)

// ---- init ----
__global__ void k_deg0() {
    int i = blockIdx.x * blockDim.x + threadIdx.x;
    if (i < NN) { g_deg[i] = 0; g_cur[i] = 0; }
}

// zero-init pack array so padding slots are (src=0, w=0)
__global__ void k_pinit() {
    int i = blockIdx.x * blockDim.x + threadIdx.x;
    if (i < EPAD) g_pack[i] = make_int2(0, 0);
}

__global__ void k_count(const int* __restrict__ col, int E) {
    int i = blockIdx.x * blockDim.x + threadIdx.x;
    if (i < E) atomicAdd(&g_deg[col[i]], 1);
}

__global__ void k_dis() {
    int i = blockIdx.x * blockDim.x + threadIdx.x;
    if (i < NN) {
        int d = g_deg[i];
        g_dis[i] = (d > 0) ? rsqrtf((float)d) : 0.f;
    }
}

// ---- exclusive scan over PADDED degrees (even per node) ----
__global__ void k_scan1() {
    __shared__ int s[1024];
    int tid = threadIdx.x;
    int i = blockIdx.x * 1024 + tid;
    int v = 0;
    if (i < NN) v = (g_deg[i] + 1) & ~1;   // pad to even
    s[tid] = v;
    __syncthreads();
    #pragma unroll
    for (int o = 1; o < 1024; o <<= 1) {
        int t = (tid >= o) ? s[tid - o] : 0;
        __syncthreads();
        s[tid] += t;
        __syncthreads();
    }
    if (i < NN) g_off[i] = s[tid] - v;
    if (tid == 1023) g_bsum[blockIdx.x] = s[1023];
}

__global__ void k_scan2() {
    __shared__ int s[256];
    int tid = threadIdx.x;
    int v = (tid < NB_SCAN) ? g_bsum[tid] : 0;
    s[tid] = v;
    __syncthreads();
    #pragma unroll
    for (int o = 1; o < 256; o <<= 1) {
        int t = (tid >= o) ? s[tid - o] : 0;
        __syncthreads();
        s[tid] += t;
        __syncthreads();
    }
    if (tid < NB_SCAN) g_bpre[tid] = s[tid] - v;
}

__global__ void k_off_final() {
    int i = blockIdx.x * blockDim.x + threadIdx.x;
    if (i < NN) g_off[i] += g_bpre[i >> 10];
}

// ---- CSR fill: packed (src, wgt); padded tail slots keep (0, 0.0f) ----
__global__ void k_fill(const int* __restrict__ row, const int* __restrict__ col, int E) {
    int e = blockIdx.x * blockDim.x + threadIdx.x;
    if (e >= E) return;
    int r = __ldg(row + e);
    int c = __ldg(col + e);
    int slot = __ldg(g_off + c) + atomicAdd(&g_cur[c], 1);
    float w = __ldg((const float*)g_dis + r) * __ldg((const float*)g_dis + c);
    g_pack[slot] = make_int2(r, __float_as_int(w));
}

// ---- gather SpMM: 16 lanes per node (natural order), float4 payload.
// Edge metadata loaded 2-at-a-time via one int4 (beg is even, pdeg is even).
// Unroll 2 pairs (4 edges) with 4 independent accumulators; remainder is
// exactly 0 or 1 pair — no scalar tail.
// layer 0: emb -> g_x1 ; layer 1: g_x1 -> g_x2
__global__ void k_gather(const float* __restrict__ emb, int layer) {
    int t = blockIdx.x * blockDim.x + threadIdx.x;
    int node = t >> 4;
    int j = t & 15;
    if (node >= NN) return;

    const float4* x  = (layer == 0) ? (const float4*)emb  : (const float4*)g_x1;
    float4*       xn = (layer == 0) ? (float4*)g_x1 : (float4*)g_x2;

    int beg  = __ldg(g_off + node);                 // even
    int pdeg = (__ldg(g_deg + node) + 1) & ~1;      // even
    const int4* packs = (const int4*)g_pack + (beg >> 1);
    int npair = pdeg >> 1;

    float4 A0 = make_float4(0.f, 0.f, 0.f, 0.f), A1 = A0, A2 = A0, A3 = A0;

    int q = 0;
    for (; q + 2 <= npair; q += 2) {
        int4 e01 = __ldg(packs + q);
        int4 e23 = __ldg(packs + q + 1);
        float4 v0 = __ldg(x + (size_t)e01.x * 16 + j);
        float4 v1 = __ldg(x + (size_t)e01.z * 16 + j);
        float4 v2 = __ldg(x + (size_t)e23.x * 16 + j);
        float4 v3 = __ldg(x + (size_t)e23.z * 16 + j);
        float w0 = __int_as_float(e01.y), w1 = __int_as_float(e01.w);
        float w2 = __int_as_float(e23.y), w3 = __int_as_float(e23.w);
        A0.x += w0 * v0.x; A0.y += w0 * v0.y; A0.z += w0 * v0.z; A0.w += w0 * v0.w;
        A1.x += w1 * v1.x; A1.y += w1 * v1.y; A1.z += w1 * v1.z; A1.w += w1 * v1.w;
        A2.x += w2 * v2.x; A2.y += w2 * v2.y; A2.z += w2 * v2.z; A2.w += w2 * v2.w;
        A3.x += w3 * v3.x; A3.y += w3 * v3.y; A3.z += w3 * v3.z; A3.w += w3 * v3.w;
    }
    if (q < npair) {
        int4 e01 = __ldg(packs + q);
        float4 v0 = __ldg(x + (size_t)e01.x * 16 + j);
        float4 v1 = __ldg(x + (size_t)e01.z * 16 + j);
        float w0 = __int_as_float(e01.y), w1 = __int_as_float(e01.w);
        A0.x += w0 * v0.x; A0.y += w0 * v0.y; A0.z += w0 * v0.z; A0.w += w0 * v0.w;
        A1.x += w1 * v1.x; A1.y += w1 * v1.y; A1.z += w1 * v1.z; A1.w += w1 * v1.w;
    }

    float4 acc;
    acc.x = (A0.x + A1.x) + (A2.x + A3.x);
    acc.y = (A0.y + A1.y) + (A2.y + A3.y);
    acc.z = (A0.z + A1.z) + (A2.z + A3.z);
    acc.w = (A0.w + A1.w) + (A2.w + A3.w);
    xn[(size_t)node * 16 + j] = acc;
}

// ---- final layer fused with alpha-combine: out = 0.25*(emb+x1+x2+gather(x2))
__global__ void k_gather_final(const float* __restrict__ emb) {
    int t = blockIdx.x * blockDim.x + threadIdx.x;
    int node = t >> 4;
    int j = t & 15;
    if (node >= NN) return;

    const float4* x = (const float4*)g_x2;
    int beg  = __ldg(g_off + node);
    int pdeg = (__ldg(g_deg + node) + 1) & ~1;
    const int4* packs = (const int4*)g_pack + (beg >> 1);
    int npair = pdeg >> 1;

    float4 A0 = make_float4(0.f, 0.f, 0.f, 0.f), A1 = A0, A2 = A0, A3 = A0;

    int q = 0;
    for (; q + 2 <= npair; q += 2) {
        int4 e01 = __ldg(packs + q);
        int4 e23 = __ldg(packs + q + 1);
        float4 v0 = __ldg(x + (size_t)e01.x * 16 + j);
        float4 v1 = __ldg(x + (size_t)e01.z * 16 + j);
        float4 v2 = __ldg(x + (size_t)e23.x * 16 + j);
        float4 v3 = __ldg(x + (size_t)e23.z * 16 + j);
        float w0 = __int_as_float(e01.y), w1 = __int_as_float(e01.w);
        float w2 = __int_as_float(e23.y), w3 = __int_as_float(e23.w);
        A0.x += w0 * v0.x; A0.y += w0 * v0.y; A0.z += w0 * v0.z; A0.w += w0 * v0.w;
        A1.x += w1 * v1.x; A1.y += w1 * v1.y; A1.z += w1 * v1.z; A1.w += w1 * v1.w;
        A2.x += w2 * v2.x; A2.y += w2 * v2.y; A2.z += w2 * v2.z; A2.w += w2 * v2.w;
        A3.x += w3 * v3.x; A3.y += w3 * v3.y; A3.z += w3 * v3.z; A3.w += w3 * v3.w;
    }
    if (q < npair) {
        int4 e01 = __ldg(packs + q);
        float4 v0 = __ldg(x + (size_t)e01.x * 16 + j);
        float4 v1 = __ldg(x + (size_t)e01.z * 16 + j);
        float w0 = __int_as_float(e01.y), w1 = __int_as_float(e01.w);
        A0.x += w0 * v0.x; A0.y += w0 * v0.y; A0.z += w0 * v0.z; A0.w += w0 * v0.w;
        A1.x += w1 * v1.x; A1.y += w1 * v1.y; A1.z += w1 * v1.z; A1.w += w1 * v1.w;
    }

    size_t idx = (size_t)node * 16 + j;
    float4 a = __ldg((const float4*)emb + idx);
    float4 b = ((const float4*)g_x1)[idx];
    float4 c = ((const float4*)g_x2)[idx];
    float4 o;
    o.x = ALPHA * (a.x + b.x + c.x + ((A0.x + A1.x) + (A2.x + A3.x)));
    o.y = ALPHA * (a.y + b.y + c.y + ((A0.y + A1.y) + (A2.y + A3.y)));
    o.z = ALPHA * (a.z + b.z + c.z + ((A0.z + A1.z) + (A2.z + A3.z)));
    o.w = ALPHA * (a.w + b.w + c.w + ((A0.w + A1.w) + (A2.w + A3.w)));
    ((float4*)g_out)[idx] = o;
}

// ---- scoring: 16 lanes per (user,item) pair, float4 loads ----
__global__ void k_score(const int* __restrict__ batch, float* __restrict__ out, int P) {
    int t = blockIdx.x * blockDim.x + threadIdx.x;
    int p = t >> 4;
    int lane = t & 15;
    if (p >= P) return;
    int u = __ldg(batch + 3 * p);
    int v = __ldg(batch + 3 * p + 1);
    float4 a = __ldg((const float4*)g_out + (size_t)u * 16 + lane);
    float4 b = __ldg((const float4*)g_out + (size_t)v * 16 + lane);
    float s = a.x * b.x + a.y * b.y + a.z * b.z + a.w * b.w;
    #pragma unroll
    for (int o = 8; o; o >>= 1) s += __shfl_xor_sync(0xFFFFFFFFu, s, o);
    if (lane == 0) out[p] = s;
}

extern "C" void kernel_launch(void* const* d_in, const int* in_sizes, int n_in,
                              void* d_out, int out_size) {
    const float* emb   = (const float*)d_in[0];
    const int*   ei    = (const int*)d_in[1];
    const int*   batch = (const int*)d_in[2];
    float*       out   = (float*)d_out;

    int E = in_sizes[1] / 2;
    const int* row = ei;
    const int* col = ei + E;
    int P = in_sizes[2] / 3;

    k_deg0<<<(NN + 255) / 256, 256>>>();
    k_pinit<<<(EPAD + 255) / 256, 256>>>();
    k_count<<<(E + 255) / 256, 256>>>(col, E);
    k_dis<<<(NN + 255) / 256, 256>>>();
    k_scan1<<<NB_SCAN, 1024>>>();
    k_scan2<<<1, 256>>>();
    k_off_final<<<(NN + 255) / 256, 256>>>();
    k_fill<<<(E + 255) / 256, 256>>>(row, col, E);

    int gthreads = NN * 16;
    int gblocks = (gthreads + 255) / 256;
    k_gather<<<gblocks, 256>>>(emb, 0);
    k_gather<<<gblocks, 256>>>(emb, 1);
    k_gather_final<<<gblocks, 256>>>(emb);

    long long sthreads = (long long)P * 16;
    k_score<<<(int)((sthreads + 255) / 256), 256>>>(batch, out, P);
}

// round 10
// speedup vs baseline: 1.1935x; 1.1837x over previous
#include <cuda_runtime.h>

#define NN   200000
#define DIM  64
#define NV   (NN * DIM)
#define EMAX 1250000
#define ALPHA 0.25f
#define NB_SCAN ((NN + 1023) / 1024)   // 196

// Scratch (device globals — no allocation allowed).
// NOTE: never pass these symbols from host code; select inside kernels.
__device__ float g_x1[NV];
__device__ float g_x2[NV];
__device__ float g_out[NV];
__device__ float g_dis[NN];
__device__ int   g_deg[NN];
__device__ int   g_off[NN];
__device__ int   g_cur[NN];
__device__ int   g_bsum[NB_SCAN];
__device__ int   g_bpre[NB_SCAN];
__device__ int   g_src[EMAX];
__device__ float g_wgt[EMAX];

// ---- init ----
__global__ void k_deg0() {
    int i = blockIdx.x * blockDim.x + threadIdx.x;
    if (i < NN) { g_deg[i] = 0; g_cur[i] = 0; }
}

__global__ void k_count(const int* __restrict__ col, int E) {
    int i = blockIdx.x * blockDim.x + threadIdx.x;
    if (i < E) atomicAdd(&g_deg[col[i]], 1);
}

// ---- scan of degrees, fused with dis = deg^{-1/2} ----
__global__ void k_scan1() {
    __shared__ int s[1024];
    int tid = threadIdx.x;
    int i = blockIdx.x * 1024 + tid;
    int v = (i < NN) ? g_deg[i] : 0;
    if (i < NN) g_dis[i] = (v > 0) ? rsqrtf((float)v) : 0.f;
    s[tid] = v;
    __syncthreads();
    #pragma unroll
    for (int o = 1; o < 1024; o <<= 1) {
        int t = (tid >= o) ? s[tid - o] : 0;
        __syncthreads();
        s[tid] += t;
        __syncthreads();
    }
    if (i < NN) g_off[i] = s[tid] - v;
    if (tid == 1023) g_bsum[blockIdx.x] = s[1023];
}

__global__ void k_scan2() {
    __shared__ int s[256];
    int tid = threadIdx.x;
    int v = (tid < NB_SCAN) ? g_bsum[tid] : 0;
    s[tid] = v;
    __syncthreads();
    #pragma unroll
    for (int o = 1; o < 256; o <<= 1) {
        int t = (tid >= o) ? s[tid - o] : 0;
        __syncthreads();
        s[tid] += t;
        __syncthreads();
    }
    if (tid < NB_SCAN) g_bpre[tid] = s[tid] - v;
}

__global__ void k_off_final() {
    int i = blockIdx.x * blockDim.x + threadIdx.x;
    if (i < NN) g_off[i] += g_bpre[i >> 10];
}

// ---- CSR fill: slot per (dst, edge) with precomputed weight ----
__global__ void k_fill(const int* __restrict__ row, const int* __restrict__ col, int E) {
    int e = blockIdx.x * blockDim.x + threadIdx.x;
    if (e >= E) return;
    int r = __ldg(row + e);
    int c = __ldg(col + e);
    int slot = __ldg(g_off + c) + atomicAdd(&g_cur[c], 1);
    g_src[slot] = r;
    g_wgt[slot] = __ldg((const float*)g_dis + r) * __ldg((const float*)g_dis + c);
}

// ---- gather SpMM (R4-exact structure): 16 lanes per node, unroll-4,
// 4 independent accumulators. Cache-policy deltas only:
//   metadata via __ldcs (streaming, don't pollute L2)
//   destination via __stcs (evict-first, keep source rows L2-resident)
// layer 0: emb -> g_x1 ; layer 1: g_x1 -> g_x2
__global__ void k_gather(const float* __restrict__ emb, int layer) {
    int t = blockIdx.x * blockDim.x + threadIdx.x;
    int node = t >> 4;
    int j = t & 15;
    if (node >= NN) return;

    const float4* x  = (layer == 0) ? (const float4*)emb  : (const float4*)g_x1;
    float4*       xn = (layer == 0) ? (float4*)g_x1 : (float4*)g_x2;

    int beg = __ldg(g_off + node);
    int end = beg + __ldg(g_deg + node);
    float4 A0 = make_float4(0.f, 0.f, 0.f, 0.f), A1 = A0, A2 = A0, A3 = A0;

    int k = beg;
    for (; k + 4 <= end; k += 4) {
        int r0 = __ldcs(g_src + k);
        int r1 = __ldcs(g_src + k + 1);
        int r2 = __ldcs(g_src + k + 2);
        int r3 = __ldcs(g_src + k + 3);
        float w0 = __ldcs(g_wgt + k);
        float w1 = __ldcs(g_wgt + k + 1);
        float w2 = __ldcs(g_wgt + k + 2);
        float w3 = __ldcs(g_wgt + k + 3);
        float4 v0 = __ldg(x + (size_t)r0 * 16 + j);
        float4 v1 = __ldg(x + (size_t)r1 * 16 + j);
        float4 v2 = __ldg(x + (size_t)r2 * 16 + j);
        float4 v3 = __ldg(x + (size_t)r3 * 16 + j);
        A0.x += w0 * v0.x; A0.y += w0 * v0.y; A0.z += w0 * v0.z; A0.w += w0 * v0.w;
        A1.x += w1 * v1.x; A1.y += w1 * v1.y; A1.z += w1 * v1.z; A1.w += w1 * v1.w;
        A2.x += w2 * v2.x; A2.y += w2 * v2.y; A2.z += w2 * v2.z; A2.w += w2 * v2.w;
        A3.x += w3 * v3.x; A3.y += w3 * v3.y; A3.z += w3 * v3.z; A3.w += w3 * v3.w;
    }
    if (k + 2 <= end) {
        int r0 = __ldcs(g_src + k);
        int r1 = __ldcs(g_src + k + 1);
        float w0 = __ldcs(g_wgt + k);
        float w1 = __ldcs(g_wgt + k + 1);
        float4 v0 = __ldg(x + (size_t)r0 * 16 + j);
        float4 v1 = __ldg(x + (size_t)r1 * 16 + j);
        A0.x += w0 * v0.x; A0.y += w0 * v0.y; A0.z += w0 * v0.z; A0.w += w0 * v0.w;
        A1.x += w1 * v1.x; A1.y += w1 * v1.y; A1.z += w1 * v1.z; A1.w += w1 * v1.w;
        k += 2;
    }
    if (k < end) {
        int r0 = __ldcs(g_src + k);
        float w0 = __ldcs(g_wgt + k);
        float4 v0 = __ldg(x + (size_t)r0 * 16 + j);
        A2.x += w0 * v0.x; A2.y += w0 * v0.y; A2.z += w0 * v0.z; A2.w += w0 * v0.w;
    }

    float4 acc;
    acc.x = (A0.x + A1.x) + (A2.x + A3.x);
    acc.y = (A0.y + A1.y) + (A2.y + A3.y);
    acc.z = (A0.z + A1.z) + (A2.z + A3.z);
    acc.w = (A0.w + A1.w) + (A2.w + A3.w);
    __stcs(xn + (size_t)node * 16 + j, acc);
}

// ---- final layer fused with alpha-combine: out = 0.25*(emb+x1+x2+gather(x2))
__global__ void k_gather_final(const float* __restrict__ emb) {
    int t = blockIdx.x * blockDim.x + threadIdx.x;
    int node = t >> 4;
    int j = t & 15;
    if (node >= NN) return;

    const float4* x = (const float4*)g_x2;
    int beg = __ldg(g_off + node);
    int end = beg + __ldg(g_deg + node);
    float4 A0 = make_float4(0.f, 0.f, 0.f, 0.f), A1 = A0, A2 = A0, A3 = A0;

    int k = beg;
    for (; k + 4 <= end; k += 4) {
        int r0 = __ldcs(g_src + k);
        int r1 = __ldcs(g_src + k + 1);
        int r2 = __ldcs(g_src + k + 2);
        int r3 = __ldcs(g_src + k + 3);
        float w0 = __ldcs(g_wgt + k);
        float w1 = __ldcs(g_wgt + k + 1);
        float w2 = __ldcs(g_wgt + k + 2);
        float w3 = __ldcs(g_wgt + k + 3);
        float4 v0 = __ldg(x + (size_t)r0 * 16 + j);
        float4 v1 = __ldg(x + (size_t)r1 * 16 + j);
        float4 v2 = __ldg(x + (size_t)r2 * 16 + j);
        float4 v3 = __ldg(x + (size_t)r3 * 16 + j);
        A0.x += w0 * v0.x; A0.y += w0 * v0.y; A0.z += w0 * v0.z; A0.w += w0 * v0.w;
        A1.x += w1 * v1.x; A1.y += w1 * v1.y; A1.z += w1 * v1.z; A1.w += w1 * v1.w;
        A2.x += w2 * v2.x; A2.y += w2 * v2.y; A2.z += w2 * v2.z; A2.w += w2 * v2.w;
        A3.x += w3 * v3.x; A3.y += w3 * v3.y; A3.z += w3 * v3.z; A3.w += w3 * v3.w;
    }
    if (k + 2 <= end) {
        int r0 = __ldcs(g_src + k);
        int r1 = __ldcs(g_src + k + 1);
        float w0 = __ldcs(g_wgt + k);
        float w1 = __ldcs(g_wgt + k + 1);
        float4 v0 = __ldg(x + (size_t)r0 * 16 + j);
        float4 v1 = __ldg(x + (size_t)r1 * 16 + j);
        A0.x += w0 * v0.x; A0.y += w0 * v0.y; A0.z += w0 * v0.z; A0.w += w0 * v0.w;
        A1.x += w1 * v1.x; A1.y += w1 * v1.y; A1.z += w1 * v1.z; A1.w += w1 * v1.w;
        k += 2;
    }
    if (k < end) {
        int r0 = __ldcs(g_src + k);
        float w0 = __ldcs(g_wgt + k);
        float4 v0 = __ldg(x + (size_t)r0 * 16 + j);
        A2.x += w0 * v0.x; A2.y += w0 * v0.y; A2.z += w0 * v0.z; A2.w += w0 * v0.w;
    }

    size_t idx = (size_t)node * 16 + j;
    float4 a = __ldg((const float4*)emb + idx);
    float4 b = ((const float4*)g_x1)[idx];
    float4 c = ((const float4*)g_x2)[idx];
    float4 o;
    o.x = ALPHA * (a.x + b.x + c.x + ((A0.x + A1.x) + (A2.x + A3.x)));
    o.y = ALPHA * (a.y + b.y + c.y + ((A0.y + A1.y) + (A2.y + A3.y)));
    o.z = ALPHA * (a.z + b.z + c.z + ((A0.z + A1.z) + (A2.z + A3.z)));
    o.w = ALPHA * (a.w + b.w + c.w + ((A0.w + A1.w) + (A2.w + A3.w)));
    ((float4*)g_out)[idx] = o;   // normal store: k_score reads it next
}

// ---- scoring: 16 lanes per (user,item) pair, float4 loads ----
__global__ void k_score(const int* __restrict__ batch, float* __restrict__ out, int P) {
    int t = blockIdx.x * blockDim.x + threadIdx.x;
    int p = t >> 4;
    int lane = t & 15;
    if (p >= P) return;
    int u = __ldg(batch + 3 * p);
    int v = __ldg(batch + 3 * p + 1);
    float4 a = __ldg((const float4*)g_out + (size_t)u * 16 + lane);
    float4 b = __ldg((const float4*)g_out + (size_t)v * 16 + lane);
    float s = a.x * b.x + a.y * b.y + a.z * b.z + a.w * b.w;
    #pragma unroll
    for (int o = 8; o; o >>= 1) s += __shfl_xor_sync(0xFFFFFFFFu, s, o);
    if (lane == 0) out[p] = s;
}

extern "C" void kernel_launch(void* const* d_in, const int* in_sizes, int n_in,
                              void* d_out, int out_size) {
    const float* emb   = (const float*)d_in[0];
    const int*   ei    = (const int*)d_in[1];
    const int*   batch = (const int*)d_in[2];
    float*       out   = (float*)d_out;

    int E = in_sizes[1] / 2;
    const int* row = ei;
    const int* col = ei + E;
    int P = in_sizes[2] / 3;

    k_deg0<<<(NN + 255) / 256, 256>>>();
    k_count<<<(E + 255) / 256, 256>>>(col, E);
    k_scan1<<<NB_SCAN, 1024>>>();
    k_scan2<<<1, 256>>>();
    k_off_final<<<(NN + 255) / 256, 256>>>();
    k_fill<<<(E + 255) / 256, 256>>>(row, col, E);

    int gthreads = NN * 16;
    int gblocks = (gthreads + 255) / 256;
    k_gather<<<gblocks, 256>>>(emb, 0);
    k_gather<<<gblocks, 256>>>(emb, 1);
    k_gather_final<<<gblocks, 256>>>(emb);

    long long sthreads = (long long)P * 16;
    k_score<<<(int)((sthreads + 255) / 256), 256>>>(batch, out, P);
}

// round 11
// speedup vs baseline: 1.4562x; 1.2201x over previous
#include <cuda_runtime.h>
#include <cuda_fp16.h>

#define NN   200000
#define DIM  64
#define NV   (NN * DIM)
#define EMAX 1250000
#define ALPHA 0.25f
#define NB_SCAN ((NN + 1023) / 1024)   // 196

// Scratch (device globals — no allocation allowed).
// NOTE: never pass these symbols from host code; select inside kernels.
// fp16 node rows: [NN][64] halves = [NN][16] uint2 (4 halves per lane).
__device__ uint2 g_h0[NN * 16];    // fp16(emb)
__device__ uint2 g_x1h[NN * 16];
__device__ uint2 g_x2h[NN * 16];
__device__ float g_out[NV];
__device__ float g_dis[NN];
__device__ int   g_deg[NN];
__device__ int   g_off[NN];
__device__ int   g_cur[NN];
__device__ int   g_bsum[NB_SCAN];
__device__ int   g_bpre[NB_SCAN];
__device__ int   g_src[EMAX];
__device__ float g_wgt[EMAX];

__device__ __forceinline__ float4 h4_to_f4(uint2 u) {
    __half2 h01 = *reinterpret_cast<__half2*>(&u.x);
    __half2 h23 = *reinterpret_cast<__half2*>(&u.y);
    float2 f01 = __half22float2(h01);
    float2 f23 = __half22float2(h23);
    return make_float4(f01.x, f01.y, f23.x, f23.y);
}

__device__ __forceinline__ uint2 f4_to_h4(float4 f) {
    __half2 h01 = __float22half2_rn(make_float2(f.x, f.y));
    __half2 h23 = __float22half2_rn(make_float2(f.z, f.w));
    uint2 u;
    u.x = *reinterpret_cast<unsigned int*>(&h01);
    u.y = *reinterpret_cast<unsigned int*>(&h23);
    return u;
}

// ---- init ----
__global__ void k_deg0() {
    int i = blockIdx.x * blockDim.x + threadIdx.x;
    if (i < NN) { g_deg[i] = 0; g_cur[i] = 0; }
}

__global__ void k_count(const int* __restrict__ col, int E) {
    int i = blockIdx.x * blockDim.x + threadIdx.x;
    if (i < E) atomicAdd(&g_deg[col[i]], 1);
}

// ---- emb -> fp16 conversion, fused with dis = deg^{-1/2} ----
__global__ void k_half_dis(const float* __restrict__ emb) {
    int i = blockIdx.x * blockDim.x + threadIdx.x;
    if (i < NV / 4) {
        float4 v = __ldg((const float4*)emb + i);
        g_h0[i] = f4_to_h4(v);
    }
    if (i < NN) {
        int d = g_deg[i];
        g_dis[i] = (d > 0) ? rsqrtf((float)d) : 0.f;
    }
}

// ---- exclusive scan of degrees ----
__global__ void k_scan1() {
    __shared__ int s[1024];
    int tid = threadIdx.x;
    int i = blockIdx.x * 1024 + tid;
    int v = (i < NN) ? g_deg[i] : 0;
    s[tid] = v;
    __syncthreads();
    #pragma unroll
    for (int o = 1; o < 1024; o <<= 1) {
        int t = (tid >= o) ? s[tid - o] : 0;
        __syncthreads();
        s[tid] += t;
        __syncthreads();
    }
    if (i < NN) g_off[i] = s[tid] - v;
    if (tid == 1023) g_bsum[blockIdx.x] = s[1023];
}

__global__ void k_scan2() {
    __shared__ int s[256];
    int tid = threadIdx.x;
    int v = (tid < NB_SCAN) ? g_bsum[tid] : 0;
    s[tid] = v;
    __syncthreads();
    #pragma unroll
    for (int o = 1; o < 256; o <<= 1) {
        int t = (tid >= o) ? s[tid - o] : 0;
        __syncthreads();
        s[tid] += t;
        __syncthreads();
    }
    if (tid < NB_SCAN) g_bpre[tid] = s[tid] - v;
}

__global__ void k_off_final() {
    int i = blockIdx.x * blockDim.x + threadIdx.x;
    if (i < NN) g_off[i] += g_bpre[i >> 10];
}

// ---- CSR fill: slot per (dst, edge) with precomputed weight ----
__global__ void k_fill(const int* __restrict__ row, const int* __restrict__ col, int E) {
    int e = blockIdx.x * blockDim.x + threadIdx.x;
    if (e >= E) return;
    int r = __ldg(row + e);
    int c = __ldg(col + e);
    int slot = __ldg(g_off + c) + atomicAdd(&g_cur[c], 1);
    g_src[slot] = r;
    g_wgt[slot] = __ldg((const float*)g_dis + r) * __ldg((const float*)g_dis + c);
}

// ---- fp16 gather SpMM (R4 structure): 16 lanes per node, unroll-4,
// 4 independent fp32 accumulators, 8B row loads (half the bytes of fp32).
// layer 0: g_h0 -> g_x1h ; layer 1: g_x1h -> g_x2h
__global__ void k_gather(int layer) {
    int t = blockIdx.x * blockDim.x + threadIdx.x;
    int node = t >> 4;
    int j = t & 15;
    if (node >= NN) return;

    const uint2* x  = (layer == 0) ? g_h0  : g_x1h;
    uint2*       xn = (layer == 0) ? g_x1h : g_x2h;

    int beg = __ldg(g_off + node);
    int end = beg + __ldg(g_deg + node);
    float4 A0 = make_float4(0.f, 0.f, 0.f, 0.f), A1 = A0, A2 = A0, A3 = A0;

    int k = beg;
    for (; k + 4 <= end; k += 4) {
        int r0 = __ldg(g_src + k);
        int r1 = __ldg(g_src + k + 1);
        int r2 = __ldg(g_src + k + 2);
        int r3 = __ldg(g_src + k + 3);
        float w0 = __ldg(g_wgt + k);
        float w1 = __ldg(g_wgt + k + 1);
        float w2 = __ldg(g_wgt + k + 2);
        float w3 = __ldg(g_wgt + k + 3);
        float4 v0 = h4_to_f4(__ldg(x + (size_t)r0 * 16 + j));
        float4 v1 = h4_to_f4(__ldg(x + (size_t)r1 * 16 + j));
        float4 v2 = h4_to_f4(__ldg(x + (size_t)r2 * 16 + j));
        float4 v3 = h4_to_f4(__ldg(x + (size_t)r3 * 16 + j));
        A0.x += w0 * v0.x; A0.y += w0 * v0.y; A0.z += w0 * v0.z; A0.w += w0 * v0.w;
        A1.x += w1 * v1.x; A1.y += w1 * v1.y; A1.z += w1 * v1.z; A1.w += w1 * v1.w;
        A2.x += w2 * v2.x; A2.y += w2 * v2.y; A2.z += w2 * v2.z; A2.w += w2 * v2.w;
        A3.x += w3 * v3.x; A3.y += w3 * v3.y; A3.z += w3 * v3.z; A3.w += w3 * v3.w;
    }
    if (k + 2 <= end) {
        int r0 = __ldg(g_src + k);
        int r1 = __ldg(g_src + k + 1);
        float w0 = __ldg(g_wgt + k);
        float w1 = __ldg(g_wgt + k + 1);
        float4 v0 = h4_to_f4(__ldg(x + (size_t)r0 * 16 + j));
        float4 v1 = h4_to_f4(__ldg(x + (size_t)r1 * 16 + j));
        A0.x += w0 * v0.x; A0.y += w0 * v0.y; A0.z += w0 * v0.z; A0.w += w0 * v0.w;
        A1.x += w1 * v1.x; A1.y += w1 * v1.y; A1.z += w1 * v1.z; A1.w += w1 * v1.w;
        k += 2;
    }
    if (k < end) {
        int r0 = __ldg(g_src + k);
        float w0 = __ldg(g_wgt + k);
        float4 v0 = h4_to_f4(__ldg(x + (size_t)r0 * 16 + j));
        A2.x += w0 * v0.x; A2.y += w0 * v0.y; A2.z += w0 * v0.z; A2.w += w0 * v0.w;
    }

    float4 acc;
    acc.x = (A0.x + A1.x) + (A2.x + A3.x);
    acc.y = (A0.y + A1.y) + (A2.y + A3.y);
    acc.z = (A0.z + A1.z) + (A2.z + A3.z);
    acc.w = (A0.w + A1.w) + (A2.w + A3.w);
    xn[(size_t)node * 16 + j] = f4_to_h4(acc);
}

// ---- final layer fused with alpha-combine:
// out = 0.25*(emb_fp32 + x1 + x2 + gather(x2)), output fp32 ----
__global__ void k_gather_final(const float* __restrict__ emb) {
    int t = blockIdx.x * blockDim.x + threadIdx.x;
    int node = t >> 4;
    int j = t & 15;
    if (node >= NN) return;

    const uint2* x = g_x2h;
    int beg = __ldg(g_off + node);
    int end = beg + __ldg(g_deg + node);
    float4 A0 = make_float4(0.f, 0.f, 0.f, 0.f), A1 = A0, A2 = A0, A3 = A0;

    int k = beg;
    for (; k + 4 <= end; k += 4) {
        int r0 = __ldg(g_src + k);
        int r1 = __ldg(g_src + k + 1);
        int r2 = __ldg(g_src + k + 2);
        int r3 = __ldg(g_src + k + 3);
        float w0 = __ldg(g_wgt + k);
        float w1 = __ldg(g_wgt + k + 1);
        float w2 = __ldg(g_wgt + k + 2);
        float w3 = __ldg(g_wgt + k + 3);
        float4 v0 = h4_to_f4(__ldg(x + (size_t)r0 * 16 + j));
        float4 v1 = h4_to_f4(__ldg(x + (size_t)r1 * 16 + j));
        float4 v2 = h4_to_f4(__ldg(x + (size_t)r2 * 16 + j));
        float4 v3 = h4_to_f4(__ldg(x + (size_t)r3 * 16 + j));
        A0.x += w0 * v0.x; A0.y += w0 * v0.y; A0.z += w0 * v0.z; A0.w += w0 * v0.w;
        A1.x += w1 * v1.x; A1.y += w1 * v1.y; A1.z += w1 * v1.z; A1.w += w1 * v1.w;
        A2.x += w2 * v2.x; A2.y += w2 * v2.y; A2.z += w2 * v2.z; A2.w += w2 * v2.w;
        A3.x += w3 * v3.x; A3.y += w3 * v3.y; A3.z += w3 * v3.z; A3.w += w3 * v3.w;
    }
    if (k + 2 <= end) {
        int r0 = __ldg(g_src + k);
        int r1 = __ldg(g_src + k + 1);
        float w0 = __ldg(g_wgt + k);
        float w1 = __ldg(g_wgt + k + 1);
        float4 v0 = h4_to_f4(__ldg(x + (size_t)r0 * 16 + j));
        float4 v1 = h4_to_f4(__ldg(x + (size_t)r1 * 16 + j));
        A0.x += w0 * v0.x; A0.y += w0 * v0.y; A0.z += w0 * v0.z; A0.w += w0 * v0.w;
        A1.x += w1 * v1.x; A1.y += w1 * v1.y; A1.z += w1 * v1.z; A1.w += w1 * v1.w;
        k += 2;
    }
    if (k < end) {
        int r0 = __ldg(g_src + k);
        float w0 = __ldg(g_wgt + k);
        float4 v0 = h4_to_f4(__ldg(x + (size_t)r0 * 16 + j));
        A2.x += w0 * v0.x; A2.y += w0 * v0.y; A2.z += w0 * v0.z; A2.w += w0 * v0.w;
    }

    size_t idx = (size_t)node * 16 + j;
    float4 a = __ldg((const float4*)emb + idx);   // exact fp32 emb term
    float4 b = h4_to_f4(g_x1h[idx]);
    float4 c = h4_to_f4(g_x2h[idx]);
    float4 o;
    o.x = ALPHA * (a.x + b.x + c.x + ((A0.x + A1.x) + (A2.x + A3.x)));
    o.y = ALPHA * (a.y + b.y + c.y + ((A0.y + A1.y) + (A2.y + A3.y)));
    o.z = ALPHA * (a.z + b.z + c.z + ((A0.z + A1.z) + (A2.z + A3.z)));
    o.w = ALPHA * (a.w + b.w + c.w + ((A0.w + A1.w) + (A2.w + A3.w)));
    ((float4*)g_out)[idx] = o;
}

// ---- scoring: 16 lanes per (user,item) pair, float4 loads (fp32 out) ----
__global__ void k_score(const int* __restrict__ batch, float* __restrict__ out, int P) {
    int t = blockIdx.x * blockDim.x + threadIdx.x;
    int p = t >> 4;
    int lane = t & 15;
    if (p >= P) return;
    int u = __ldg(batch + 3 * p);
    int v = __ldg(batch + 3 * p + 1);
    float4 a = __ldg((const float4*)g_out + (size_t)u * 16 + lane);
    float4 b = __ldg((const float4*)g_out + (size_t)v * 16 + lane);
    float s = a.x * b.x + a.y * b.y + a.z * b.z + a.w * b.w;
    #pragma unroll
    for (int o = 8; o; o >>= 1) s += __shfl_xor_sync(0xFFFFFFFFu, s, o);
    if (lane == 0) out[p] = s;
}

extern "C" void kernel_launch(void* const* d_in, const int* in_sizes, int n_in,
                              void* d_out, int out_size) {
    const float* emb   = (const float*)d_in[0];
    const int*   ei    = (const int*)d_in[1];
    const int*   batch = (const int*)d_in[2];
    float*       out   = (float*)d_out;

    int E = in_sizes[1] / 2;
    const int* row = ei;
    const int* col = ei + E;
    int P = in_sizes[2] / 3;

    k_deg0<<<(NN + 255) / 256, 256>>>();
    k_count<<<(E + 255) / 256, 256>>>(col, E);
    k_half_dis<<<(NV / 4 + 255) / 256, 256>>>(emb);
    k_scan1<<<NB_SCAN, 1024>>>();
    k_scan2<<<1, 256>>>();
    k_off_final<<<(NN + 255) / 256, 256>>>();
    k_fill<<<(E + 255) / 256, 256>>>(row, col, E);

    int gthreads = NN * 16;
    int gblocks = (gthreads + 255) / 256;
    k_gather<<<gblocks, 256>>>(0);
    k_gather<<<gblocks, 256>>>(1);
    k_gather_final<<<gblocks, 256>>>(emb);

    long long sthreads = (long long)P * 16;
    k_score<<<(int)((sthreads + 255) / 256), 256>>>(batch, out, P);
}

// round 12
// speedup vs baseline: 1.4852x; 1.0199x over previous
#include <cuda_runtime.h>
#include <cuda_fp16.h>

#define NN   200000
#define DIM  64
#define NV   (NN * DIM)
#define EMAX 1250000
#define ALPHA 0.25f
#define NB_SCAN ((NN + 1023) / 1024)   // 196

// Scratch (device globals — no allocation allowed).
// NOTE: never pass these symbols from host code; select inside kernels.
// fp16 node rows: [NN][64] halves = [NN][16] uint2 (4 halves per lane).
__device__ uint2 g_h0[NN * 16];    // fp16(emb)
__device__ uint2 g_x1h[NN * 16];
__device__ uint2 g_x2h[NN * 16];
__device__ uint2 g_outh[NN * 16];  // fp16 final embedding
__device__ float g_dis[NN];
__device__ int   g_deg[NN];
__device__ int   g_off[NN];
__device__ int   g_cur[NN];
__device__ int   g_bsum[NB_SCAN];
__device__ int   g_bpre[NB_SCAN];
__device__ int   g_src[EMAX];
__device__ float g_wgt[EMAX];

__device__ __forceinline__ float4 h4_to_f4(uint2 u) {
    __half2 h01 = *reinterpret_cast<__half2*>(&u.x);
    __half2 h23 = *reinterpret_cast<__half2*>(&u.y);
    float2 f01 = __half22float2(h01);
    float2 f23 = __half22float2(h23);
    return make_float4(f01.x, f01.y, f23.x, f23.y);
}

__device__ __forceinline__ uint2 f4_to_h4(float4 f) {
    __half2 h01 = __float22half2_rn(make_float2(f.x, f.y));
    __half2 h23 = __float22half2_rn(make_float2(f.z, f.w));
    uint2 u;
    u.x = *reinterpret_cast<unsigned int*>(&h01);
    u.y = *reinterpret_cast<unsigned int*>(&h23);
    return u;
}

// ---- init ----
__global__ void k_deg0() {
    int i = blockIdx.x * blockDim.x + threadIdx.x;
    if (i < NN) { g_deg[i] = 0; g_cur[i] = 0; }
}

__global__ void k_count(const int* __restrict__ col, int E) {
    int i = blockIdx.x * blockDim.x + threadIdx.x;
    if (i < E) atomicAdd(&g_deg[col[i]], 1);
}

// ---- emb -> fp16 conversion, fused with dis = deg^{-1/2} ----
__global__ void k_half_dis(const float* __restrict__ emb) {
    int i = blockIdx.x * blockDim.x + threadIdx.x;
    if (i < NV / 4) {
        float4 v = __ldg((const float4*)emb + i);
        g_h0[i] = f4_to_h4(v);
    }
    if (i < NN) {
        int d = g_deg[i];
        g_dis[i] = (d > 0) ? rsqrtf((float)d) : 0.f;
    }
}

// ---- exclusive scan of degrees ----
__global__ void k_scan1() {
    __shared__ int s[1024];
    int tid = threadIdx.x;
    int i = blockIdx.x * 1024 + tid;
    int v = (i < NN) ? g_deg[i] : 0;
    s[tid] = v;
    __syncthreads();
    #pragma unroll
    for (int o = 1; o < 1024; o <<= 1) {
        int t = (tid >= o) ? s[tid - o] : 0;
        __syncthreads();
        s[tid] += t;
        __syncthreads();
    }
    if (i < NN) g_off[i] = s[tid] - v;
    if (tid == 1023) g_bsum[blockIdx.x] = s[1023];
}

__global__ void k_scan2() {
    __shared__ int s[256];
    int tid = threadIdx.x;
    int v = (tid < NB_SCAN) ? g_bsum[tid] : 0;
    s[tid] = v;
    __syncthreads();
    #pragma unroll
    for (int o = 1; o < 256; o <<= 1) {
        int t = (tid >= o) ? s[tid - o] : 0;
        __syncthreads();
        s[tid] += t;
        __syncthreads();
    }
    if (tid < NB_SCAN) g_bpre[tid] = s[tid] - v;
}

__global__ void k_off_final() {
    int i = blockIdx.x * blockDim.x + threadIdx.x;
    if (i < NN) g_off[i] += g_bpre[i >> 10];
}

// ---- CSR fill: slot per (dst, edge) with precomputed weight ----
__global__ void k_fill(const int* __restrict__ row, const int* __restrict__ col, int E) {
    int e = blockIdx.x * blockDim.x + threadIdx.x;
    if (e >= E) return;
    int r = __ldg(row + e);
    int c = __ldg(col + e);
    int slot = __ldg(g_off + c) + atomicAdd(&g_cur[c], 1);
    g_src[slot] = r;
    g_wgt[slot] = __ldg((const float*)g_dis + r) * __ldg((const float*)g_dis + c);
}

// ---- fp16 gather SpMM (R4 structure): 16 lanes per node, unroll-4,
// 4 independent fp32 accumulators, 8B row loads.
// layer 0: g_h0 -> g_x1h ; layer 1: g_x1h -> g_x2h
__global__ void k_gather(int layer) {
    int t = blockIdx.x * blockDim.x + threadIdx.x;
    int node = t >> 4;
    int j = t & 15;
    if (node >= NN) return;

    const uint2* x  = (layer == 0) ? g_h0  : g_x1h;
    uint2*       xn = (layer == 0) ? g_x1h : g_x2h;

    int beg = __ldg(g_off + node);
    int end = beg + __ldg(g_deg + node);
    float4 A0 = make_float4(0.f, 0.f, 0.f, 0.f), A1 = A0, A2 = A0, A3 = A0;

    int k = beg;
    for (; k + 4 <= end; k += 4) {
        int r0 = __ldg(g_src + k);
        int r1 = __ldg(g_src + k + 1);
        int r2 = __ldg(g_src + k + 2);
        int r3 = __ldg(g_src + k + 3);
        float w0 = __ldg(g_wgt + k);
        float w1 = __ldg(g_wgt + k + 1);
        float w2 = __ldg(g_wgt + k + 2);
        float w3 = __ldg(g_wgt + k + 3);
        float4 v0 = h4_to_f4(__ldg(x + (size_t)r0 * 16 + j));
        float4 v1 = h4_to_f4(__ldg(x + (size_t)r1 * 16 + j));
        float4 v2 = h4_to_f4(__ldg(x + (size_t)r2 * 16 + j));
        float4 v3 = h4_to_f4(__ldg(x + (size_t)r3 * 16 + j));
        A0.x += w0 * v0.x; A0.y += w0 * v0.y; A0.z += w0 * v0.z; A0.w += w0 * v0.w;
        A1.x += w1 * v1.x; A1.y += w1 * v1.y; A1.z += w1 * v1.z; A1.w += w1 * v1.w;
        A2.x += w2 * v2.x; A2.y += w2 * v2.y; A2.z += w2 * v2.z; A2.w += w2 * v2.w;
        A3.x += w3 * v3.x; A3.y += w3 * v3.y; A3.z += w3 * v3.z; A3.w += w3 * v3.w;
    }
    if (k + 2 <= end) {
        int r0 = __ldg(g_src + k);
        int r1 = __ldg(g_src + k + 1);
        float w0 = __ldg(g_wgt + k);
        float w1 = __ldg(g_wgt + k + 1);
        float4 v0 = h4_to_f4(__ldg(x + (size_t)r0 * 16 + j));
        float4 v1 = h4_to_f4(__ldg(x + (size_t)r1 * 16 + j));
        A0.x += w0 * v0.x; A0.y += w0 * v0.y; A0.z += w0 * v0.z; A0.w += w0 * v0.w;
        A1.x += w1 * v1.x; A1.y += w1 * v1.y; A1.z += w1 * v1.z; A1.w += w1 * v1.w;
        k += 2;
    }
    if (k < end) {
        int r0 = __ldg(g_src + k);
        float w0 = __ldg(g_wgt + k);
        float4 v0 = h4_to_f4(__ldg(x + (size_t)r0 * 16 + j));
        A2.x += w0 * v0.x; A2.y += w0 * v0.y; A2.z += w0 * v0.z; A2.w += w0 * v0.w;
    }

    float4 acc;
    acc.x = (A0.x + A1.x) + (A2.x + A3.x);
    acc.y = (A0.y + A1.y) + (A2.y + A3.y);
    acc.z = (A0.z + A1.z) + (A2.z + A3.z);
    acc.w = (A0.w + A1.w) + (A2.w + A3.w);
    xn[(size_t)node * 16 + j] = f4_to_h4(acc);
}

// ---- final layer fused with alpha-combine, fp16 output:
// outh = fp16( 0.25*(emb_fp32 + x1 + x2 + gather(x2)) ) ----
__global__ void k_gather_final(const float* __restrict__ emb) {
    int t = blockIdx.x * blockDim.x + threadIdx.x;
    int node = t >> 4;
    int j = t & 15;
    if (node >= NN) return;

    const uint2* x = g_x2h;
    int beg = __ldg(g_off + node);
    int end = beg + __ldg(g_deg + node);
    float4 A0 = make_float4(0.f, 0.f, 0.f, 0.f), A1 = A0, A2 = A0, A3 = A0;

    int k = beg;
    for (; k + 4 <= end; k += 4) {
        int r0 = __ldg(g_src + k);
        int r1 = __ldg(g_src + k + 1);
        int r2 = __ldg(g_src + k + 2);
        int r3 = __ldg(g_src + k + 3);
        float w0 = __ldg(g_wgt + k);
        float w1 = __ldg(g_wgt + k + 1);
        float w2 = __ldg(g_wgt + k + 2);
        float w3 = __ldg(g_wgt + k + 3);
        float4 v0 = h4_to_f4(__ldg(x + (size_t)r0 * 16 + j));
        float4 v1 = h4_to_f4(__ldg(x + (size_t)r1 * 16 + j));
        float4 v2 = h4_to_f4(__ldg(x + (size_t)r2 * 16 + j));
        float4 v3 = h4_to_f4(__ldg(x + (size_t)r3 * 16 + j));
        A0.x += w0 * v0.x; A0.y += w0 * v0.y; A0.z += w0 * v0.z; A0.w += w0 * v0.w;
        A1.x += w1 * v1.x; A1.y += w1 * v1.y; A1.z += w1 * v1.z; A1.w += w1 * v1.w;
        A2.x += w2 * v2.x; A2.y += w2 * v2.y; A2.z += w2 * v2.z; A2.w += w2 * v2.w;
        A3.x += w3 * v3.x; A3.y += w3 * v3.y; A3.z += w3 * v3.z; A3.w += w3 * v3.w;
    }
    if (k + 2 <= end) {
        int r0 = __ldg(g_src + k);
        int r1 = __ldg(g_src + k + 1);
        float w0 = __ldg(g_wgt + k);
        float w1 = __ldg(g_wgt + k + 1);
        float4 v0 = h4_to_f4(__ldg(x + (size_t)r0 * 16 + j));
        float4 v1 = h4_to_f4(__ldg(x + (size_t)r1 * 16 + j));
        A0.x += w0 * v0.x; A0.y += w0 * v0.y; A0.z += w0 * v0.z; A0.w += w0 * v0.w;
        A1.x += w1 * v1.x; A1.y += w1 * v1.y; A1.z += w1 * v1.z; A1.w += w1 * v1.w;
        k += 2;
    }
    if (k < end) {
        int r0 = __ldg(g_src + k);
        float w0 = __ldg(g_wgt + k);
        float4 v0 = h4_to_f4(__ldg(x + (size_t)r0 * 16 + j));
        A2.x += w0 * v0.x; A2.y += w0 * v0.y; A2.z += w0 * v0.z; A2.w += w0 * v0.w;
    }

    size_t idx = (size_t)node * 16 + j;
    float4 a = __ldg((const float4*)emb + idx);   // exact fp32 emb term
    float4 b = h4_to_f4(g_x1h[idx]);
    float4 c = h4_to_f4(g_x2h[idx]);
    float4 o;
    o.x = ALPHA * (a.x + b.x + c.x + ((A0.x + A1.x) + (A2.x + A3.x)));
    o.y = ALPHA * (a.y + b.y + c.y + ((A0.y + A1.y) + (A2.y + A3.y)));
    o.z = ALPHA * (a.z + b.z + c.z + ((A0.z + A1.z) + (A2.z + A3.z)));
    o.w = ALPHA * (a.w + b.w + c.w + ((A0.w + A1.w) + (A2.w + A3.w)));
    g_outh[idx] = f4_to_h4(o);
}

// ---- scoring: 16 lanes per (user,item) pair, fp16 rows, fp32 accumulate ----
__global__ void k_score(const int* __restrict__ batch, float* __restrict__ out, int P) {
    int t = blockIdx.x * blockDim.x + threadIdx.x;
    int p = t >> 4;
    int lane = t & 15;
    if (p >= P) return;
    int u = __ldg(batch + 3 * p);
    int v = __ldg(batch + 3 * p + 1);
    float4 a = h4_to_f4(__ldg(g_outh + (size_t)u * 16 + lane));
    float4 b = h4_to_f4(__ldg(g_outh + (size_t)v * 16 + lane));
    float s = a.x * b.x + a.y * b.y + a.z * b.z + a.w * b.w;
    #pragma unroll
    for (int o = 8; o; o >>= 1) s += __shfl_xor_sync(0xFFFFFFFFu, s, o);
    if (lane == 0) out[p] = s;
}

extern "C" void kernel_launch(void* const* d_in, const int* in_sizes, int n_in,
                              void* d_out, int out_size) {
    const float* emb   = (const float*)d_in[0];
    const int*   ei    = (const int*)d_in[1];
    const int*   batch = (const int*)d_in[2];
    float*       out   = (float*)d_out;

    int E = in_sizes[1] / 2;
    const int* row = ei;
    const int* col = ei + E;
    int P = in_sizes[2] / 3;

    k_deg0<<<(NN + 255) / 256, 256>>>();
    k_count<<<(E + 255) / 256, 256>>>(col, E);
    k_half_dis<<<(NV / 4 + 255) / 256, 256>>>(emb);
    k_scan1<<<NB_SCAN, 1024>>>();
    k_scan2<<<1, 256>>>();
    k_off_final<<<(NN + 255) / 256, 256>>>();
    k_fill<<<(E + 255) / 256, 256>>>(row, col, E);

    int gthreads = NN * 16;
    int gblocks = (gthreads + 255) / 256;
    k_gather<<<gblocks, 256>>>(0);
    k_gather<<<gblocks, 256>>>(1);
    k_gather_final<<<gblocks, 256>>>(emb);

    long long sthreads = (long long)P * 16;
    k_score<<<(int)((sthreads + 255) / 256), 256>>>(batch, out, P);
}

// round 13
// speedup vs baseline: 1.6334x; 1.0998x over previous
#include <cuda_runtime.h>
#include <cuda_fp16.h>

#define NN   200000
#define DIM  64
#define NV   (NN * DIM)
#define EMAX 1250000
#define ALPHA 0.25f
#define NB_SCAN ((NN + 1023) / 1024)   // 196

// Scratch (device globals — no allocation allowed).
// NOTE: never pass these symbols from host code; select inside kernels.
// fp16 node rows: [NN][64] halves = [NN][16] uint2 (4 halves per lane).
__device__ uint2 g_h0[NN * 16];    // fp16(emb)
__device__ uint2 g_x1h[NN * 16];
__device__ uint2 g_x2h[NN * 16];
__device__ uint2 g_outh[NN * 16];  // fp16 final embedding
__device__ float g_dis[NN];
__device__ int   g_deg[NN];
__device__ int   g_off[NN];
__device__ int   g_cur[NN];
__device__ int   g_bsum[NB_SCAN];
__device__ int   g_bpre[NB_SCAN];
__device__ int   g_src[EMAX];
__device__ float g_wgt[EMAX];

__device__ __forceinline__ float4 h4_to_f4(uint2 u) {
    __half2 h01 = *reinterpret_cast<__half2*>(&u.x);
    __half2 h23 = *reinterpret_cast<__half2*>(&u.y);
    float2 f01 = __half22float2(h01);
    float2 f23 = __half22float2(h23);
    return make_float4(f01.x, f01.y, f23.x, f23.y);
}

__device__ __forceinline__ uint2 f4_to_h4(float4 f) {
    __half2 h01 = __float22half2_rn(make_float2(f.x, f.y));
    __half2 h23 = __float22half2_rn(make_float2(f.z, f.w));
    uint2 u;
    u.x = *reinterpret_cast<unsigned int*>(&h01);
    u.y = *reinterpret_cast<unsigned int*>(&h23);
    return u;
}

// ---- init ----
__global__ void k_deg0() {
    int i = blockIdx.x * blockDim.x + threadIdx.x;
    if (i < NN) { g_deg[i] = 0; g_cur[i] = 0; }
}

// ---- degree count fused with emb -> fp16 conversion (independent work) ----
__global__ void k_count_half(const int* __restrict__ col,
                             const float* __restrict__ emb, int E) {
    int i = blockIdx.x * blockDim.x + threadIdx.x;
    if (i < E) atomicAdd(&g_deg[col[i]], 1);
    if (i < NV / 4) {
        float4 v = __ldg((const float4*)emb + i);
        g_h0[i] = f4_to_h4(v);
    }
}

// ---- scan of degrees, fused with dis = deg^{-1/2} ----
__global__ void k_scan1() {
    __shared__ int s[1024];
    int tid = threadIdx.x;
    int i = blockIdx.x * 1024 + tid;
    int v = (i < NN) ? g_deg[i] : 0;
    if (i < NN) g_dis[i] = (v > 0) ? rsqrtf((float)v) : 0.f;
    s[tid] = v;
    __syncthreads();
    #pragma unroll
    for (int o = 1; o < 1024; o <<= 1) {
        int t = (tid >= o) ? s[tid - o] : 0;
        __syncthreads();
        s[tid] += t;
        __syncthreads();
    }
    if (i < NN) g_off[i] = s[tid] - v;
    if (tid == 1023) g_bsum[blockIdx.x] = s[1023];
}

__global__ void k_scan2() {
    __shared__ int s[256];
    int tid = threadIdx.x;
    int v = (tid < NB_SCAN) ? g_bsum[tid] : 0;
    s[tid] = v;
    __syncthreads();
    #pragma unroll
    for (int o = 1; o < 256; o <<= 1) {
        int t = (tid >= o) ? s[tid - o] : 0;
        __syncthreads();
        s[tid] += t;
        __syncthreads();
    }
    if (tid < NB_SCAN) g_bpre[tid] = s[tid] - v;
}

__global__ void k_off_final() {
    int i = blockIdx.x * blockDim.x + threadIdx.x;
    if (i < NN) g_off[i] += g_bpre[i >> 10];
}

// ---- CSR fill: slot per (dst, edge) with precomputed weight ----
__global__ void k_fill(const int* __restrict__ row, const int* __restrict__ col, int E) {
    int e = blockIdx.x * blockDim.x + threadIdx.x;
    if (e >= E) return;
    int r = __ldg(row + e);
    int c = __ldg(col + e);
    int slot = __ldg(g_off + c) + atomicAdd(&g_cur[c], 1);
    g_src[slot] = r;
    g_wgt[slot] = __ldg((const float*)g_dis + r) * __ldg((const float*)g_dis + c);
}

// ---- fp16 gather SpMM (R4 structure): 16 lanes per node, unroll-4,
// 4 independent fp32 accumulators, 8B row loads.
// layer 0: g_h0 -> g_x1h ; layer 1: g_x1h -> g_x2h
__global__ void k_gather(int layer) {
    int t = blockIdx.x * blockDim.x + threadIdx.x;
    int node = t >> 4;
    int j = t & 15;
    if (node >= NN) return;

    const uint2* x  = (layer == 0) ? g_h0  : g_x1h;
    uint2*       xn = (layer == 0) ? g_x1h : g_x2h;

    int beg = __ldg(g_off + node);
    int end = beg + __ldg(g_deg + node);
    float4 A0 = make_float4(0.f, 0.f, 0.f, 0.f), A1 = A0, A2 = A0, A3 = A0;

    int k = beg;
    for (; k + 4 <= end; k += 4) {
        int r0 = __ldg(g_src + k);
        int r1 = __ldg(g_src + k + 1);
        int r2 = __ldg(g_src + k + 2);
        int r3 = __ldg(g_src + k + 3);
        float w0 = __ldg(g_wgt + k);
        float w1 = __ldg(g_wgt + k + 1);
        float w2 = __ldg(g_wgt + k + 2);
        float w3 = __ldg(g_wgt + k + 3);
        float4 v0 = h4_to_f4(__ldg(x + (size_t)r0 * 16 + j));
        float4 v1 = h4_to_f4(__ldg(x + (size_t)r1 * 16 + j));
        float4 v2 = h4_to_f4(__ldg(x + (size_t)r2 * 16 + j));
        float4 v3 = h4_to_f4(__ldg(x + (size_t)r3 * 16 + j));
        A0.x += w0 * v0.x; A0.y += w0 * v0.y; A0.z += w0 * v0.z; A0.w += w0 * v0.w;
        A1.x += w1 * v1.x; A1.y += w1 * v1.y; A1.z += w1 * v1.z; A1.w += w1 * v1.w;
        A2.x += w2 * v2.x; A2.y += w2 * v2.y; A2.z += w2 * v2.z; A2.w += w2 * v2.w;
        A3.x += w3 * v3.x; A3.y += w3 * v3.y; A3.z += w3 * v3.z; A3.w += w3 * v3.w;
    }
    if (k + 2 <= end) {
        int r0 = __ldg(g_src + k);
        int r1 = __ldg(g_src + k + 1);
        float w0 = __ldg(g_wgt + k);
        float w1 = __ldg(g_wgt + k + 1);
        float4 v0 = h4_to_f4(__ldg(x + (size_t)r0 * 16 + j));
        float4 v1 = h4_to_f4(__ldg(x + (size_t)r1 * 16 + j));
        A0.x += w0 * v0.x; A0.y += w0 * v0.y; A0.z += w0 * v0.z; A0.w += w0 * v0.w;
        A1.x += w1 * v1.x; A1.y += w1 * v1.y; A1.z += w1 * v1.z; A1.w += w1 * v1.w;
        k += 2;
    }
    if (k < end) {
        int r0 = __ldg(g_src + k);
        float w0 = __ldg(g_wgt + k);
        float4 v0 = h4_to_f4(__ldg(x + (size_t)r0 * 16 + j));
        A2.x += w0 * v0.x; A2.y += w0 * v0.y; A2.z += w0 * v0.z; A2.w += w0 * v0.w;
    }

    float4 acc;
    acc.x = (A0.x + A1.x) + (A2.x + A3.x);
    acc.y = (A0.y + A1.y) + (A2.y + A3.y);
    acc.z = (A0.z + A1.z) + (A2.z + A3.z);
    acc.w = (A0.w + A1.w) + (A2.w + A3.w);
    xn[(size_t)node * 16 + j] = f4_to_h4(acc);
}

// ---- final layer fused with alpha-combine, all-fp16 operands:
// outh = fp16( 0.25*(h0 + x1 + x2 + gather(x2)) ) ----
__global__ void k_gather_final() {
    int t = blockIdx.x * blockDim.x + threadIdx.x;
    int node = t >> 4;
    int j = t & 15;
    if (node >= NN) return;

    const uint2* x = g_x2h;
    int beg = __ldg(g_off + node);
    int end = beg + __ldg(g_deg + node);
    float4 A0 = make_float4(0.f, 0.f, 0.f, 0.f), A1 = A0, A2 = A0, A3 = A0;

    int k = beg;
    for (; k + 4 <= end; k += 4) {
        int r0 = __ldg(g_src + k);
        int r1 = __ldg(g_src + k + 1);
        int r2 = __ldg(g_src + k + 2);
        int r3 = __ldg(g_src + k + 3);
        float w0 = __ldg(g_wgt + k);
        float w1 = __ldg(g_wgt + k + 1);
        float w2 = __ldg(g_wgt + k + 2);
        float w3 = __ldg(g_wgt + k + 3);
        float4 v0 = h4_to_f4(__ldg(x + (size_t)r0 * 16 + j));
        float4 v1 = h4_to_f4(__ldg(x + (size_t)r1 * 16 + j));
        float4 v2 = h4_to_f4(__ldg(x + (size_t)r2 * 16 + j));
        float4 v3 = h4_to_f4(__ldg(x + (size_t)r3 * 16 + j));
        A0.x += w0 * v0.x; A0.y += w0 * v0.y; A0.z += w0 * v0.z; A0.w += w0 * v0.w;
        A1.x += w1 * v1.x; A1.y += w1 * v1.y; A1.z += w1 * v1.z; A1.w += w1 * v1.w;
        A2.x += w2 * v2.x; A2.y += w2 * v2.y; A2.z += w2 * v2.z; A2.w += w2 * v2.w;
        A3.x += w3 * v3.x; A3.y += w3 * v3.y; A3.z += w3 * v3.z; A3.w += w3 * v3.w;
    }
    if (k + 2 <= end) {
        int r0 = __ldg(g_src + k);
        int r1 = __ldg(g_src + k + 1);
        float w0 = __ldg(g_wgt + k);
        float w1 = __ldg(g_wgt + k + 1);
        float4 v0 = h4_to_f4(__ldg(x + (size_t)r0 * 16 + j));
        float4 v1 = h4_to_f4(__ldg(x + (size_t)r1 * 16 + j));
        A0.x += w0 * v0.x; A0.y += w0 * v0.y; A0.z += w0 * v0.z; A0.w += w0 * v0.w;
        A1.x += w1 * v1.x; A1.y += w1 * v1.y; A1.z += w1 * v1.z; A1.w += w1 * v1.w;
        k += 2;
    }
    if (k < end) {
        int r0 = __ldg(g_src + k);
        float w0 = __ldg(g_wgt + k);
        float4 v0 = h4_to_f4(__ldg(x + (size_t)r0 * 16 + j));
        A2.x += w0 * v0.x; A2.y += w0 * v0.y; A2.z += w0 * v0.z; A2.w += w0 * v0.w;
    }

    size_t idx = (size_t)node * 16 + j;
    float4 a = h4_to_f4(g_h0[idx]);     // fp16 emb copy (saves fp32 stream)
    float4 b = h4_to_f4(g_x1h[idx]);
    float4 c = h4_to_f4(g_x2h[idx]);
    float4 o;
    o.x = ALPHA * (a.x + b.x + c.x + ((A0.x + A1.x) + (A2.x + A3.x)));
    o.y = ALPHA * (a.y + b.y + c.y + ((A0.y + A1.y) + (A2.y + A3.y)));
    o.z = ALPHA * (a.z + b.z + c.z + ((A0.z + A1.z) + (A2.z + A3.z)));
    o.w = ALPHA * (a.w + b.w + c.w + ((A0.w + A1.w) + (A2.w + A3.w)));
    g_outh[idx] = f4_to_h4(o);
}

// ---- scoring: 8 lanes per (user,item) pair, 16B fp16 loads, fp32 acc ----
__global__ void k_score(const int* __restrict__ batch, float* __restrict__ out, int P) {
    int t = blockIdx.x * blockDim.x + threadIdx.x;
    int p = t >> 3;
    int lane = t & 7;
    if (p >= P) return;
    int u = __ldg(batch + 3 * p);
    int v = __ldg(batch + 3 * p + 1);
    uint4 ua = __ldg((const uint4*)g_outh + (size_t)u * 8 + lane);
    uint4 ub = __ldg((const uint4*)g_outh + (size_t)v * 8 + lane);
    float4 a0 = h4_to_f4(make_uint2(ua.x, ua.y));
    float4 a1 = h4_to_f4(make_uint2(ua.z, ua.w));
    float4 b0 = h4_to_f4(make_uint2(ub.x, ub.y));
    float4 b1 = h4_to_f4(make_uint2(ub.z, ub.w));
    float s = a0.x * b0.x + a0.y * b0.y + a0.z * b0.z + a0.w * b0.w
            + a1.x * b1.x + a1.y * b1.y + a1.z * b1.z + a1.w * b1.w;
    #pragma unroll
    for (int o = 4; o; o >>= 1) s += __shfl_xor_sync(0xFFFFFFFFu, s, o);
    if (lane == 0) out[p] = s;
}

extern "C" void kernel_launch(void* const* d_in, const int* in_sizes, int n_in,
                              void* d_out, int out_size) {
    const float* emb   = (const float*)d_in[0];
    const int*   ei    = (const int*)d_in[1];
    const int*   batch = (const int*)d_in[2];
    float*       out   = (float*)d_out;

    int E = in_sizes[1] / 2;
    const int* row = ei;
    const int* col = ei + E;
    int P = in_sizes[2] / 3;

    k_deg0<<<(NN + 255) / 256, 256>>>();
    k_count_half<<<(NV / 4 + 255) / 256, 256>>>(col, emb, E);
    k_scan1<<<NB_SCAN, 1024>>>();
    k_scan2<<<1, 256>>>();
    k_off_final<<<(NN + 255) / 256, 256>>>();
    k_fill<<<(E + 255) / 256, 256>>>(row, col, E);

    int gthreads = NN * 16;
    int gblocks = (gthreads + 255) / 256;
    k_gather<<<gblocks, 256>>>(0);
    k_gather<<<gblocks, 256>>>(1);
    k_gather_final<<<gblocks, 256>>>();

    long long sthreads = (long long)P * 8;
    k_score<<<(int)((sthreads + 255) / 256), 256>>>(batch, out, P);
}

// round 14
// speedup vs baseline: 1.6692x; 1.0219x over previous
#include <cuda_runtime.h>
#include <cuda_fp16.h>

#define NN   200000
#define DIM  64
#define NV   (NN * DIM)
#define EMAX 1250000
#define ALPHA 0.25f
#define NB_SCAN ((NN + 1023) / 1024)   // 196

// Scratch (device globals — no allocation allowed).
// NOTE: never pass these symbols from host code; select inside kernels.
// fp16 node rows: [NN][64] halves = [NN][16] uint2 (4 halves per lane).
// g_deg/g_cur are zeroed at the END of each launch (by k_score); BSS zero
// covers the very first call. Every call does identical work.
__device__ uint2 g_h0[NN * 16];    // fp16(emb)
__device__ uint2 g_x1h[NN * 16];
__device__ uint2 g_x2h[NN * 16];
__device__ uint2 g_outh[NN * 16];  // fp16 final embedding
__device__ float g_dis[NN];
__device__ int   g_deg[NN];
__device__ int   g_off[NN];        // block-local exclusive prefix
__device__ int   g_cur[NN];
__device__ int   g_bsum[NB_SCAN];
__device__ int   g_bpre[NB_SCAN];
__device__ int   g_src[EMAX];
__device__ float g_wgt[EMAX];

__device__ __forceinline__ float4 h4_to_f4(uint2 u) {
    __half2 h01 = *reinterpret_cast<__half2*>(&u.x);
    __half2 h23 = *reinterpret_cast<__half2*>(&u.y);
    float2 f01 = __half22float2(h01);
    float2 f23 = __half22float2(h23);
    return make_float4(f01.x, f01.y, f23.x, f23.y);
}

__device__ __forceinline__ uint2 f4_to_h4(float4 f) {
    __half2 h01 = __float22half2_rn(make_float2(f.x, f.y));
    __half2 h23 = __float22half2_rn(make_float2(f.z, f.w));
    uint2 u;
    u.x = *reinterpret_cast<unsigned int*>(&h01);
    u.y = *reinterpret_cast<unsigned int*>(&h23);
    return u;
}

// ---- degree count fused with emb -> fp16 conversion (independent work) ----
// Requires g_deg == 0 on entry (BSS init / zeroed by previous k_score).
__global__ void k_count_half(const int* __restrict__ col,
                             const float* __restrict__ emb, int E) {
    int i = blockIdx.x * blockDim.x + threadIdx.x;
    if (i < E) atomicAdd(&g_deg[col[i]], 1);
    if (i < NV / 4) {
        float4 v = __ldg((const float4*)emb + i);
        g_h0[i] = f4_to_h4(v);
    }
}

// ---- block scan of degrees (warp-shuffle), fused with dis = deg^{-1/2} ----
__global__ void k_scan1() {
    __shared__ int wsum[32];
    int tid = threadIdx.x;
    int lane = tid & 31, wid = tid >> 5;
    int i = blockIdx.x * 1024 + tid;
    int v = (i < NN) ? g_deg[i] : 0;
    if (i < NN) g_dis[i] = (v > 0) ? rsqrtf((float)v) : 0.f;

    int x = v;
    #pragma unroll
    for (int o = 1; o < 32; o <<= 1) {
        int y = __shfl_up_sync(0xFFFFFFFFu, x, o);
        if (lane >= o) x += y;
    }
    if (lane == 31) wsum[wid] = x;
    __syncthreads();
    if (wid == 0) {
        int s = wsum[lane];
        #pragma unroll
        for (int o = 1; o < 32; o <<= 1) {
            int y = __shfl_up_sync(0xFFFFFFFFu, s, o);
            if (lane >= o) s += y;
        }
        wsum[lane] = s;
    }
    __syncthreads();
    int incl = x + ((wid > 0) ? wsum[wid - 1] : 0);
    if (i < NN) g_off[i] = incl - v;   // block-local exclusive
    if (tid == 1023) g_bsum[blockIdx.x] = incl;
}

// ---- scan of block sums (196 elements) ----
__global__ void k_scan2() {
    __shared__ int s[256];
    int tid = threadIdx.x;
    int v = (tid < NB_SCAN) ? g_bsum[tid] : 0;
    s[tid] = v;
    __syncthreads();
    #pragma unroll
    for (int o = 1; o < 256; o <<= 1) {
        int t = (tid >= o) ? s[tid - o] : 0;
        __syncthreads();
        s[tid] += t;
        __syncthreads();
    }
    if (tid < NB_SCAN) g_bpre[tid] = s[tid] - v;
}

// ---- CSR fill: block prefix folded in; slot per (dst, edge) ----
// Requires g_cur == 0 on entry (BSS init / zeroed by previous k_score).
__global__ void k_fill(const int* __restrict__ row, const int* __restrict__ col, int E) {
    int e = blockIdx.x * blockDim.x + threadIdx.x;
    if (e >= E) return;
    int r = __ldg(row + e);
    int c = __ldg(col + e);
    int slot = __ldg(g_off + c) + __ldg(g_bpre + (c >> 10)) + atomicAdd(&g_cur[c], 1);
    g_src[slot] = r;
    g_wgt[slot] = __ldg((const float*)g_dis + r) * __ldg((const float*)g_dis + c);
}

// ---- fp16 gather SpMM (R4 structure): 16 lanes per node, unroll-4,
// 4 independent fp32 accumulators, 8B row loads.
// layer 0: g_h0 -> g_x1h ; layer 1: g_x1h -> g_x2h
__global__ void k_gather(int layer) {
    int t = blockIdx.x * blockDim.x + threadIdx.x;
    int node = t >> 4;
    int j = t & 15;
    if (node >= NN) return;

    const uint2* x  = (layer == 0) ? g_h0  : g_x1h;
    uint2*       xn = (layer == 0) ? g_x1h : g_x2h;

    int beg = __ldg(g_off + node) + __ldg(g_bpre + (node >> 10));
    int end = beg + __ldg(g_deg + node);
    float4 A0 = make_float4(0.f, 0.f, 0.f, 0.f), A1 = A0, A2 = A0, A3 = A0;

    int k = beg;
    for (; k + 4 <= end; k += 4) {
        int r0 = __ldg(g_src + k);
        int r1 = __ldg(g_src + k + 1);
        int r2 = __ldg(g_src + k + 2);
        int r3 = __ldg(g_src + k + 3);
        float w0 = __ldg(g_wgt + k);
        float w1 = __ldg(g_wgt + k + 1);
        float w2 = __ldg(g_wgt + k + 2);
        float w3 = __ldg(g_wgt + k + 3);
        float4 v0 = h4_to_f4(__ldg(x + (size_t)r0 * 16 + j));
        float4 v1 = h4_to_f4(__ldg(x + (size_t)r1 * 16 + j));
        float4 v2 = h4_to_f4(__ldg(x + (size_t)r2 * 16 + j));
        float4 v3 = h4_to_f4(__ldg(x + (size_t)r3 * 16 + j));
        A0.x += w0 * v0.x; A0.y += w0 * v0.y; A0.z += w0 * v0.z; A0.w += w0 * v0.w;
        A1.x += w1 * v1.x; A1.y += w1 * v1.y; A1.z += w1 * v1.z; A1.w += w1 * v1.w;
        A2.x += w2 * v2.x; A2.y += w2 * v2.y; A2.z += w2 * v2.z; A2.w += w2 * v2.w;
        A3.x += w3 * v3.x; A3.y += w3 * v3.y; A3.z += w3 * v3.z; A3.w += w3 * v3.w;
    }
    if (k + 2 <= end) {
        int r0 = __ldg(g_src + k);
        int r1 = __ldg(g_src + k + 1);
        float w0 = __ldg(g_wgt + k);
        float w1 = __ldg(g_wgt + k + 1);
        float4 v0 = h4_to_f4(__ldg(x + (size_t)r0 * 16 + j));
        float4 v1 = h4_to_f4(__ldg(x + (size_t)r1 * 16 + j));
        A0.x += w0 * v0.x; A0.y += w0 * v0.y; A0.z += w0 * v0.z; A0.w += w0 * v0.w;
        A1.x += w1 * v1.x; A1.y += w1 * v1.y; A1.z += w1 * v1.z; A1.w += w1 * v1.w;
        k += 2;
    }
    if (k < end) {
        int r0 = __ldg(g_src + k);
        float w0 = __ldg(g_wgt + k);
        float4 v0 = h4_to_f4(__ldg(x + (size_t)r0 * 16 + j));
        A2.x += w0 * v0.x; A2.y += w0 * v0.y; A2.z += w0 * v0.z; A2.w += w0 * v0.w;
    }

    float4 acc;
    acc.x = (A0.x + A1.x) + (A2.x + A3.x);
    acc.y = (A0.y + A1.y) + (A2.y + A3.y);
    acc.z = (A0.z + A1.z) + (A2.z + A3.z);
    acc.w = (A0.w + A1.w) + (A2.w + A3.w);
    xn[(size_t)node * 16 + j] = f4_to_h4(acc);
}

// ---- final layer fused with alpha-combine, all-fp16 operands:
// outh = fp16( 0.25*(h0 + x1 + x2 + gather(x2)) ) ----
__global__ void k_gather_final() {
    int t = blockIdx.x * blockDim.x + threadIdx.x;
    int node = t >> 4;
    int j = t & 15;
    if (node >= NN) return;

    const uint2* x = g_x2h;
    int beg = __ldg(g_off + node) + __ldg(g_bpre + (node >> 10));
    int end = beg + __ldg(g_deg + node);
    float4 A0 = make_float4(0.f, 0.f, 0.f, 0.f), A1 = A0, A2 = A0, A3 = A0;

    int k = beg;
    for (; k + 4 <= end; k += 4) {
        int r0 = __ldg(g_src + k);
        int r1 = __ldg(g_src + k + 1);
        int r2 = __ldg(g_src + k + 2);
        int r3 = __ldg(g_src + k + 3);
        float w0 = __ldg(g_wgt + k);
        float w1 = __ldg(g_wgt + k + 1);
        float w2 = __ldg(g_wgt + k + 2);
        float w3 = __ldg(g_wgt + k + 3);
        float4 v0 = h4_to_f4(__ldg(x + (size_t)r0 * 16 + j));
        float4 v1 = h4_to_f4(__ldg(x + (size_t)r1 * 16 + j));
        float4 v2 = h4_to_f4(__ldg(x + (size_t)r2 * 16 + j));
        float4 v3 = h4_to_f4(__ldg(x + (size_t)r3 * 16 + j));
        A0.x += w0 * v0.x; A0.y += w0 * v0.y; A0.z += w0 * v0.z; A0.w += w0 * v0.w;
        A1.x += w1 * v1.x; A1.y += w1 * v1.y; A1.z += w1 * v1.z; A1.w += w1 * v1.w;
        A2.x += w2 * v2.x; A2.y += w2 * v2.y; A2.z += w2 * v2.z; A2.w += w2 * v2.w;
        A3.x += w3 * v3.x; A3.y += w3 * v3.y; A3.z += w3 * v3.z; A3.w += w3 * v3.w;
    }
    if (k + 2 <= end) {
        int r0 = __ldg(g_src + k);
        int r1 = __ldg(g_src + k + 1);
        float w0 = __ldg(g_wgt + k);
        float w1 = __ldg(g_wgt + k + 1);
        float4 v0 = h4_to_f4(__ldg(x + (size_t)r0 * 16 + j));
        float4 v1 = h4_to_f4(__ldg(x + (size_t)r1 * 16 + j));
        A0.x += w0 * v0.x; A0.y += w0 * v0.y; A0.z += w0 * v0.z; A0.w += w0 * v0.w;
        A1.x += w1 * v1.x; A1.y += w1 * v1.y; A1.z += w1 * v1.z; A1.w += w1 * v1.w;
        k += 2;
    }
    if (k < end) {
        int r0 = __ldg(g_src + k);
        float w0 = __ldg(g_wgt + k);
        float4 v0 = h4_to_f4(__ldg(x + (size_t)r0 * 16 + j));
        A2.x += w0 * v0.x; A2.y += w0 * v0.y; A2.z += w0 * v0.z; A2.w += w0 * v0.w;
    }

    size_t idx = (size_t)node * 16 + j;
    float4 a = h4_to_f4(g_h0[idx]);
    float4 b = h4_to_f4(g_x1h[idx]);
    float4 c = h4_to_f4(g_x2h[idx]);
    float4 o;
    o.x = ALPHA * (a.x + b.x + c.x + ((A0.x + A1.x) + (A2.x + A3.x)));
    o.y = ALPHA * (a.y + b.y + c.y + ((A0.y + A1.y) + (A2.y + A3.y)));
    o.z = ALPHA * (a.z + b.z + c.z + ((A0.z + A1.z) + (A2.z + A3.z)));
    o.w = ALPHA * (a.w + b.w + c.w + ((A0.w + A1.w) + (A2.w + A3.w)));
    g_outh[idx] = f4_to_h4(o);
}

// ---- scoring: 8 lanes per pair, 16B fp16 loads, fp32 acc.
// Also re-zeroes g_deg/g_cur for the next invocation (consumed already). ----
__global__ void k_score(const int* __restrict__ batch, float* __restrict__ out, int P) {
    int t = blockIdx.x * blockDim.x + threadIdx.x;
    if (t < NN) { g_deg[t] = 0; g_cur[t] = 0; }
    int p = t >> 3;
    int lane = t & 7;
    if (p >= P) return;
    int u = __ldg(batch + 3 * p);
    int v = __ldg(batch + 3 * p + 1);
    uint4 ua = __ldg((const uint4*)g_outh + (size_t)u * 8 + lane);
    uint4 ub = __ldg((const uint4*)g_outh + (size_t)v * 8 + lane);
    float4 a0 = h4_to_f4(make_uint2(ua.x, ua.y));
    float4 a1 = h4_to_f4(make_uint2(ua.z, ua.w));
    float4 b0 = h4_to_f4(make_uint2(ub.x, ub.y));
    float4 b1 = h4_to_f4(make_uint2(ub.z, ub.w));
    float s = a0.x * b0.x + a0.y * b0.y + a0.z * b0.z + a0.w * b0.w
            + a1.x * b1.x + a1.y * b1.y + a1.z * b1.z + a1.w * b1.w;
    #pragma unroll
    for (int o = 4; o; o >>= 1) s += __shfl_xor_sync(0xFFFFFFFFu, s, o);
    if (lane == 0) out[p] = s;
}

extern "C" void kernel_launch(void* const* d_in, const int* in_sizes, int n_in,
                              void* d_out, int out_size) {
    const float* emb   = (const float*)d_in[0];
    const int*   ei    = (const int*)d_in[1];
    const int*   batch = (const int*)d_in[2];
    float*       out   = (float*)d_out;

    int E = in_sizes[1] / 2;
    const int* row = ei;
    const int* col = ei + E;
    int P = in_sizes[2] / 3;

    k_count_half<<<(NV / 4 + 255) / 256, 256>>>(col, emb, E);
    k_scan1<<<NB_SCAN, 1024>>>();
    k_scan2<<<1, 256>>>();
    k_fill<<<(E + 255) / 256, 256>>>(row, col, E);

    int gthreads = NN * 16;
    int gblocks = (gthreads + 255) / 256;
    k_gather<<<gblocks, 256>>>(0);
    k_gather<<<gblocks, 256>>>(1);
    k_gather_final<<<gblocks, 256>>>();

    long long sthreads = (long long)P * 8;
    k_score<<<(int)((sthreads + 255) / 256), 256>>>(batch, out, P);
}